// round 15
// baseline (speedup 1.0000x reference)
#include <cuda_runtime.h>
#include <cstdint>

#define NN 8192
#define HH 256
#define TOPK 16
#define NSEC 11
#define NEG_SLOPE 0.2f
#define CCH 8            // column chunks (32 cols each)
#define CW  32
#define RT  128          // rows per score tile
#define NTILE (NN / RT)  // 64
#define CAP 2048         // compacted members per sector (E[m]~372)
#define NEMIT 64         // emit blocks in kernel 2
#define GRID2 (NSEC + NEMIT)   // 75 blocks, single wave on 148 SMs

// ---------------- device scratch (no allocations allowed) ----------------
__device__ __align__(16) float g_p1[CCH][NN];   // partial s1 per column chunk
__device__ __align__(16) float g_p2[CCH][NN];   // partial s2 per column chunk
__device__ int      g_mask_mode;                // 0=u8, 1=i32, 2=f32
__device__ int      g_tidx[NSEC][TOPK];
__device__ float    g_ts2[NSEC][TOPK];
__device__ int      g_tcnt[NSEC];
__device__ unsigned g_ready = 0, g_fin = 0;

// ---------------- helpers ----------------
__device__ __forceinline__ bool is_active(const void* am, int i, int mode) {
    if (mode == 0) return ((const unsigned char*)am)[i] != 0;
    if (mode == 1) return ((const int*)am)[i] != 0;
    return ((const float*)am)[i] != 0.0f;
}

__device__ __forceinline__ unsigned long long umax64(unsigned long long a,
                                                     unsigned long long b) {
    return a > b ? a : b;
}

__device__ __forceinline__ float sum8(const float (*p)[NN], int i) {
    return ((p[0][i] + p[1][i]) + (p[2][i] + p[3][i])) +
           ((p[4][i] + p[5][i]) + (p[6][i] + p[7][i]));
}

// ============================================================================
// Kernel 1 (CCH*NTILE + 1 = 513 blocks, 256 threads): fused proj + scores.
// Block (chunk, tile): v1/v2 for its 32-col chunk from W (32KB, L2-shared),
// then partial dots of its 128 E-rows: g_p{1,2}[chunk][row].
// Extra last block detects the active_mask dtype (hidden under the others).
// ============================================================================
__global__ void __launch_bounds__(256)
k_scores(const float* __restrict__ E, const float* __restrict__ W,
         const float* __restrict__ a, const unsigned char* __restrict__ am) {
    int t = threadIdx.x;
    int lane = t & 31, wp = t >> 5;

    if (blockIdx.x == CCH * NTILE) {
        // ---- detect active_mask dtype: scan first NN bytes as uint4 ----
        __shared__ unsigned s_g[8], s_o[8], s_a[8];
        const uint4* am4 = (const uint4*)am;
        unsigned gt1 = 0, nzo = 0, nza = 0;
#pragma unroll
        for (int it = 0; it < NN / (256 * 16); it++) {   // 2 iterations
            uint4 v = am4[t + it * 256];
            unsigned ws[4] = {v.x, v.y, v.z, v.w};
#pragma unroll
            for (int j = 0; j < 4; j++) {
                unsigned w = ws[j];
                gt1 |= (w & 0xFEFEFEFEu);   // any byte with bits 1..7 set
                nza |= (w & 0x000000FFu);   // byte at p%4==0
                nzo |= (w & 0xFFFFFF00u);   // bytes at p%4!=0
            }
        }
        unsigned bg = __ballot_sync(0xFFFFFFFFu, gt1 != 0);
        unsigned bo = __ballot_sync(0xFFFFFFFFu, nzo != 0);
        unsigned ba = __ballot_sync(0xFFFFFFFFu, nza != 0);
        if (lane == 0) { s_g[wp] = bg; s_o[wp] = bo; s_a[wp] = ba; }
        __syncthreads();
        if (t == 0) {
            unsigned G = 0, O = 0, A = 0;
#pragma unroll
            for (int j = 0; j < 8; j++) { G |= s_g[j]; O |= s_o[j]; A |= s_a[j]; }
            int mode;
            if (G) mode = A ? 0 : 2;        // f32 truth bytes at p%4==2,3
            else   mode = O ? 0 : 1;
            g_mask_mode = mode;
        }
        return;
    }

    int chunk = blockIdx.x & (CCH - 1);
    int tile  = blockIdx.x >> 3;
    int c0f4  = chunk * (CW / 4);           // chunk col offset in float4 (8)

    __shared__ float  sa1[HH], sa2[HH];
    __shared__ float4 red1[32][8], red2[32][8];
    __shared__ float4 sv1[8], sv2[8];

    sa1[t] = a[t];
    sa2[t] = a[HH + t];
    __syncthreads();

    // ---- proj for this chunk: v[c] = sum_k W[k,c]*a[k], c in chunk ----
    {
        int cg = t & 7;                     // float4 col group within chunk
        int ks = t >> 3;                    // 32 k-subsets of 8 rows each
        const float4* W4 = (const float4*)W;
        float4 a1v = make_float4(0.f, 0.f, 0.f, 0.f);
        float4 a2v = make_float4(0.f, 0.f, 0.f, 0.f);
#pragma unroll
        for (int kk = 0; kk < 8; kk++) {
            int k = ks * 8 + kk;
            float4 w = W4[k * 64 + c0f4 + cg];
            float x1 = sa1[k], x2 = sa2[k];
            a1v.x = fmaf(w.x, x1, a1v.x); a1v.y = fmaf(w.y, x1, a1v.y);
            a1v.z = fmaf(w.z, x1, a1v.z); a1v.w = fmaf(w.w, x1, a1v.w);
            a2v.x = fmaf(w.x, x2, a2v.x); a2v.y = fmaf(w.y, x2, a2v.y);
            a2v.z = fmaf(w.z, x2, a2v.z); a2v.w = fmaf(w.w, x2, a2v.w);
        }
        red1[ks][cg] = a1v;
        red2[ks][cg] = a2v;
    }
    __syncthreads();
    if (t < 16) {
        int which = t >> 3, cg = t & 7;
        float4 s = make_float4(0.f, 0.f, 0.f, 0.f);
#pragma unroll
        for (int ks = 0; ks < 32; ks++) {
            float4 x = which ? red2[ks][cg] : red1[ks][cg];
            s.x += x.x; s.y += x.y; s.z += x.z; s.w += x.w;
        }
        if (which) sv2[cg] = s; else sv1[cg] = s;
    }
    __syncthreads();

    // ---- partial scores: 8 warps x 16 rows, quarter-warp (8 ln) per row.
    //      Prefetch all 4 row-loads (MLP=4 per lane) before reductions. ----
    int qw = lane >> 3, ql = lane & 7;
    const float4* E4 = (const float4*)E;
    float4 v = sv1[ql];
    float4 u = sv2[ql];
    int row0 = tile * RT + wp * 16 + qw;
    float4 xs[4];
#pragma unroll
    for (int r = 0; r < 4; r++)
        xs[r] = E4[(size_t)(row0 + r * 4) * 64 + c0f4 + ql];
#pragma unroll
    for (int r = 0; r < 4; r++) {
        float4 x = xs[r];
        float d1 = fmaf(x.x, v.x, fmaf(x.y, v.y, fmaf(x.z, v.z, x.w * v.w)));
        float d2 = fmaf(x.x, u.x, fmaf(x.y, u.y, fmaf(x.z, u.z, x.w * u.w)));
#pragma unroll
        for (int o = 4; o; o >>= 1) {
            d1 += __shfl_xor_sync(0xFFFFFFFFu, d1, o);
            d2 += __shfl_xor_sync(0xFFFFFFFFu, d2, o);
        }
        if (ql == 0) {
            int row = row0 + r * 4;
            g_p1[chunk][row] = d1;
            g_p2[chunk][row] = d2;
        }
    }
}

// ============================================================================
// Kernel 2 (75 blocks, 512 threads): producer-consumer in one launch.
//   blocks 0..10  : per-sector top-16 (compaction + single-warp tournament),
//                   publish tables, fence, atomicAdd(g_ready).
//   blocks 11..74 : emit; independent preamble first (overlaps with topk),
//                   then spin until g_ready==NSEC, read tables, store output.
// All 75 blocks are co-resident (single wave on 148 SMs) -> spin is safe.
// Topk result set is order-independent (max over unique keys) ->
// deterministic. Key = (monotone_u32(s2)<<32) | ~j => (s2 desc, idx asc).
// ============================================================================
__global__ void __launch_bounds__(512, 1)
k_topk_emit(const int* __restrict__ sector, const void* __restrict__ am,
            float* __restrict__ out, int out_size) {
    int bid  = blockIdx.x;
    int t    = threadIdx.x;            // 512
    int lane = t & 31, wp = t >> 5;
    int mode = g_mask_mode;

    if (bid < NSEC) {
        // ---------------- topk producer ----------------
        int sec = bid;
        __shared__ unsigned long long keys[CAP];
        __shared__ int s_n;
        if (t == 0) s_n = 0;
        __syncthreads();

#pragma unroll 1
        for (int it = 0; it < NN / 512; it++) {    // 16 iterations
            int i = t + it * 512;
            bool mem = (sector[i] == sec) && is_active(am, i, mode);
            unsigned long long key = 0ull;
            if (mem) {
                float s2 = sum8(g_p2, i);
                unsigned u = __float_as_uint(s2);
                u = (u & 0x80000000u) ? ~u : (u | 0x80000000u);
                key = ((unsigned long long)u << 32) | (unsigned)(~i);
            }
            unsigned bal = __ballot_sync(0xFFFFFFFFu, mem);
            int nb  = __popc(bal);
            int ldr = nb ? (__ffs(bal) - 1) : 0;
            int base = 0;
            if (nb && lane == ldr) base = atomicAdd(&s_n, nb);
            base = __shfl_sync(0xFFFFFFFFu, base, ldr);
            if (mem) {
                int pos = base + __popc(bal & ((1u << lane) - 1u));
                if (pos < CAP) keys[pos] = key;
            }
        }
        __syncthreads();

        if (wp == 0) {
            int M = s_n < CAP ? s_n : CAP;
            int cnt = 0;
#pragma unroll 1
            for (int r = 0; r < TOPK; r++) {
                unsigned long long m = 0ull;
                int mi = -1;
                for (int j = lane; j < M; j += 32) {
                    unsigned long long v = keys[j];
                    if (v > m) { m = v; mi = j; }
                }
                unsigned long long w = m;
#pragma unroll
                for (int o = 16; o; o >>= 1)
                    w = umax64(w, __shfl_xor_sync(0xFFFFFFFFu, w, o));
                if (w == 0ull) break;
                if (m == w && mi >= 0) keys[mi] = 0ull;   // unique key
                if (lane == 0) {
                    unsigned hi = (unsigned)(w >> 32);
                    g_tidx[sec][r] = (int)(~(unsigned)(w & 0xFFFFFFFFull));
                    g_ts2[sec][r]  = __uint_as_float(
                        (hi & 0x80000000u) ? (hi & 0x7FFFFFFFu) : ~hi);
                }
                cnt = r + 1;
            }
            if (lane == 0) {
                // fill remaining slots with smallest NON-member indices
                // (-inf ties; jax top_k picks them in ascending index order)
                int k = cnt, j = 0;
                while (k < TOPK && j < NN) {
                    bool mem = (sector[j] == sec) && is_active(am, j, mode);
                    if (!mem) { g_tidx[sec][k] = j; g_ts2[sec][k] = 0.f; k++; }
                    j++;
                }
                while (k < TOPK) { g_tidx[sec][k] = 0; g_ts2[sec][k] = 0.f; k++; }
                g_tcnt[sec] = cnt;
                // publish: all table writes above were by this thread
                __threadfence();
                atomicAdd(&g_ready, 1u);
            }
        }
    } else {
        // ---------------- emit consumer ----------------
        int eb   = bid - NSEC;             // 0..63
        int rl   = t >> 2;                 // local row 0..127
        int quad = t & 3;                  // which k-quad
        int row  = eb * 128 + rl;

        // independent preamble (overlaps with topk blocks)
        bool act = is_active(am, row, mode);
        int  sc  = sector[row];
        float s1 = 0.f;
        if (act) s1 = sum8(g_p1, row);

        // wait for all sector tables
        if (t == 0) {
            while (*(volatile unsigned*)&g_ready < (unsigned)NSEC)
                __nanosleep(32);
        }
        __syncthreads();
        __threadfence();

        __shared__ int   s_idx[NSEC][TOPK];
        __shared__ float s_s2[NSEC][TOPK];
        __shared__ int   s_cnt[NSEC];
        for (int q = t; q < NSEC * TOPK; q += 512) {
            int s = q >> 4, k = q & 15;
            s_idx[s][k] = g_tidx[s][k];
            s_s2[s][k]  = g_ts2[s][k];
            if (k == 0) s_cnt[s] = g_tcnt[s];
        }
        __syncthreads();

        int cnt = s_cnt[sc];
        const int NT = NN * TOPK;
        bool w_idx = (out_size >= 2 * NT);
        bool w_val = (out_size >= 3 * NT);
        float wv[4], iv[4], vv[4];
#pragma unroll
        for (int q = 0; q < 4; q++) {
            int kk = quad * 4 + q;
            if (!act) {
                // whole row is -inf: top_k returns indices 0..15, invalid
                wv[q] = 0.f; iv[q] = (float)kk; vv[q] = 0.f;
            } else if (kk < cnt) {
                float x = s1 + s_s2[sc][kk];
                wv[q] = (x >= 0.f) ? x : NEG_SLOPE * x;   // leaky_relu, T=1
                iv[q] = (float)s_idx[sc][kk]; vv[q] = 1.f;
            } else {
                wv[q] = 0.f; iv[q] = (float)s_idx[sc][kk]; vv[q] = 0.f;
            }
        }
        int o = row * TOPK + quad * 4;
        *(float4*)&out[o] = make_float4(wv[0], wv[1], wv[2], wv[3]);
        if (w_idx) *(float4*)&out[NT + o] =
            make_float4(iv[0], iv[1], iv[2], iv[3]);
        if (w_val) *(float4*)&out[2 * NT + o] =
            make_float4(vv[0], vv[1], vv[2], vv[3]);
    }

    // ---- reset flag state for the next graph replay (last block) ----
    __threadfence();
    __syncthreads();
    if (t == 0) {
        unsigned old = atomicAdd(&g_fin, 1u);
        if (old == (unsigned)GRID2 - 1) {
            atomicExch(&g_ready, 0u);
            atomicExch(&g_fin, 0u);
        }
    }
}

extern "C" void kernel_launch(void* const* d_in, const int* in_sizes, int n_in,
                              void* d_out, int out_size) {
    const float* E      = (const float*)d_in[0];   // embeddings [N, H]
    const float* W      = (const float*)d_in[1];   // W [H, H]
    const float* a      = (const float*)d_in[2];   // a [2H]
    const int*   sector = (const int*)d_in[3];     // sector_ids [N]
    const void*  am     = d_in[4];                 // active_mask [N]
    float* out = (float*)d_out;

    k_scores   <<<CCH * NTILE + 1, 256>>>(E, W, a, (const unsigned char*)am);
    k_topk_emit<<<GRID2, 512>>>(sector, am, out, out_size);
}

// round 16
// speedup vs baseline: 1.4729x; 1.4729x over previous
#include <cuda_runtime.h>
#include <cstdint>

#define NN 8192
#define HH 256
#define TOPK 16
#define NSEC 11
#define NEG_SLOPE 0.2f
#define CCH 8            // column chunks (32 cols each)
#define CW  32
#define RT  128          // rows per score tile
#define NTILE (NN / RT)  // 64
#define CAP 2048         // compacted members per sector (E[m]~372)

// ---------------- device scratch (no allocations allowed) ----------------
// Transposed partial layout: row-major [NN][8] so consumers read 2 float4.
__device__ __align__(16) float g_p1T[NN][CCH];
__device__ __align__(16) float g_p2T[NN][CCH];
__device__ int   g_tidx[NSEC][TOPK];
__device__ float g_ts2[NSEC][TOPK];
__device__ int   g_tcnt[NSEC];

// ---------------- helpers ----------------
__device__ __forceinline__ bool is_active(const void* am, int i, int mode) {
    if (mode == 0) return ((const unsigned char*)am)[i] != 0;
    if (mode == 1) return ((const int*)am)[i] != 0;
    return ((const float*)am)[i] != 0.0f;
}

__device__ __forceinline__ unsigned long long umax64(unsigned long long a,
                                                     unsigned long long b) {
    return a > b ? a : b;
}

__device__ __forceinline__ float sum_row(const float* p) {
    const float4* r = (const float4*)p;
    float4 x = r[0], y = r[1];
    return ((x.x + x.y) + (x.z + x.w)) + ((y.x + y.y) + (y.z + y.w));
}

__device__ __forceinline__ void pdl_trigger() {
#if defined(__CUDA_ARCH__) && __CUDA_ARCH__ >= 900
    cudaTriggerProgrammaticLaunchCompletion();
#endif
}
__device__ __forceinline__ void pdl_wait() {
#if defined(__CUDA_ARCH__) && __CUDA_ARCH__ >= 900
    cudaGridDependencySynchronize();
#endif
}

// Block-local active_mask dtype detect: scan first NN bytes as uint4.
// Valid for every candidate layout (u8 buffer is exactly NN bytes; 4-byte
// layouts are 4*NN). Returns 0=u8, 1=i32, 2=f32. Needs >=512 threads.
template <int NT_>
__device__ __forceinline__ int detect_mode(const unsigned char* am) {
    __shared__ unsigned s_g[NT_ / 32], s_o[NT_ / 32], s_a[NT_ / 32];
    __shared__ int s_mode;
    int t = threadIdx.x, lane = t & 31, wp = t >> 5;
    unsigned gt1 = 0, nzo = 0, nza = 0;
    for (int p = t; p < NN / 16; p += NT_) {
        uint4 v = ((const uint4*)am)[p];
        unsigned ws[4] = {v.x, v.y, v.z, v.w};
#pragma unroll
        for (int j = 0; j < 4; j++) {
            unsigned w = ws[j];
            gt1 |= (w & 0xFEFEFEFEu);   // any byte with bits 1..7 set
            nza |= (w & 0x000000FFu);   // byte at p%4==0
            nzo |= (w & 0xFFFFFF00u);   // bytes at p%4!=0
        }
    }
    unsigned bg = __ballot_sync(0xFFFFFFFFu, gt1 != 0);
    unsigned bo = __ballot_sync(0xFFFFFFFFu, nzo != 0);
    unsigned ba = __ballot_sync(0xFFFFFFFFu, nza != 0);
    if (lane == 0) { s_g[wp] = bg; s_o[wp] = bo; s_a[wp] = ba; }
    __syncthreads();
    if (t == 0) {
        unsigned G = 0, O = 0, A = 0;
#pragma unroll
        for (int j = 0; j < NT_ / 32; j++) { G |= s_g[j]; O |= s_o[j]; A |= s_a[j]; }
        int mode;
        if (G) mode = A ? 0 : 2;        // f32 truth bytes live at p%4==2,3
        else   mode = O ? 0 : 1;
        s_mode = mode;
    }
    __syncthreads();
    return s_mode;
}

// ============================================================================
// Kernel 1 (512 blocks, 256 threads): fused proj + partial scores.
// Block (chunk, tile): v1/v2 for its 32-col chunk from W (32KB, L2-shared),
// then partial dots of its 128 E-rows into g_p{1,2}T[row][chunk].
// ============================================================================
__global__ void __launch_bounds__(256)
k_scores(const float* __restrict__ E, const float* __restrict__ W,
         const float* __restrict__ a) {
    pdl_trigger();                      // let k_topk launch immediately
    int t = threadIdx.x;
    int lane = t & 31, wp = t >> 5;
    int chunk = blockIdx.x & (CCH - 1);
    int tile  = blockIdx.x >> 3;
    int c0f4  = chunk * (CW / 4);       // chunk col offset in float4 (8)

    __shared__ float  sa1[HH], sa2[HH];
    __shared__ float4 red1[32][8], red2[32][8];
    __shared__ float4 sv1[8], sv2[8];

    sa1[t] = a[t];
    sa2[t] = a[HH + t];
    __syncthreads();

    // ---- proj for this chunk: v[c] = sum_k W[k,c]*a[k], c in chunk ----
    {
        int cg = t & 7;                 // float4 col group within chunk
        int ks = t >> 3;                // 32 k-subsets of 8 rows each
        const float4* W4 = (const float4*)W;
        float4 a1v = make_float4(0.f, 0.f, 0.f, 0.f);
        float4 a2v = make_float4(0.f, 0.f, 0.f, 0.f);
#pragma unroll
        for (int kk = 0; kk < 8; kk++) {
            int k = ks * 8 + kk;
            float4 w = W4[k * 64 + c0f4 + cg];
            float x1 = sa1[k], x2 = sa2[k];
            a1v.x = fmaf(w.x, x1, a1v.x); a1v.y = fmaf(w.y, x1, a1v.y);
            a1v.z = fmaf(w.z, x1, a1v.z); a1v.w = fmaf(w.w, x1, a1v.w);
            a2v.x = fmaf(w.x, x2, a2v.x); a2v.y = fmaf(w.y, x2, a2v.y);
            a2v.z = fmaf(w.z, x2, a2v.z); a2v.w = fmaf(w.w, x2, a2v.w);
        }
        red1[ks][cg] = a1v;
        red2[ks][cg] = a2v;
    }
    __syncthreads();
    if (t < 16) {
        int which = t >> 3, cg = t & 7;
        float4 s = make_float4(0.f, 0.f, 0.f, 0.f);
#pragma unroll
        for (int ks = 0; ks < 32; ks++) {
            float4 x = which ? red2[ks][cg] : red1[ks][cg];
            s.x += x.x; s.y += x.y; s.z += x.z; s.w += x.w;
        }
        if (which) sv2[cg] = s; else sv1[cg] = s;
    }
    __syncthreads();

    // ---- partial scores: 8 warps x 16 rows, quarter-warp (8 ln) per row.
    //      Prefetch all 4 row-loads (MLP=4 per lane) before reductions. ----
    int qw = lane >> 3, ql = lane & 7;
    const float4* E4 = (const float4*)E;
    float4 v = sv1[ql];
    float4 u = sv2[ql];
    int row0 = tile * RT + wp * 16 + qw;
    float4 xs[4];
#pragma unroll
    for (int r = 0; r < 4; r++)
        xs[r] = E4[(size_t)(row0 + r * 4) * 64 + c0f4 + ql];
#pragma unroll
    for (int r = 0; r < 4; r++) {
        float4 x = xs[r];
        float d1 = fmaf(x.x, v.x, fmaf(x.y, v.y, fmaf(x.z, v.z, x.w * v.w)));
        float d2 = fmaf(x.x, u.x, fmaf(x.y, u.y, fmaf(x.z, u.z, x.w * u.w)));
#pragma unroll
        for (int o = 4; o; o >>= 1) {
            d1 += __shfl_xor_sync(0xFFFFFFFFu, d1, o);
            d2 += __shfl_xor_sync(0xFFFFFFFFu, d2, o);
        }
        if (ql == 0) {
            int row = row0 + r * 4;
            g_p1T[row][chunk] = d1;
            g_p2T[row][chunk] = d2;
        }
    }
}

// ============================================================================
// Kernel 2 (NSEC blocks, 1024 threads), PDL-secondary to k_scores.
// Pre-sync (overlaps k_scores): local detect + compaction of member INDICES
// (depends only on sector/am). Post-sync: load s2 for the ~372 compacted
// members, single-warp tournament, write tables. Result set is order-
// independent (max over unique keys) -> deterministic.
// Key = (monotone_u32(s2)<<32) | ~j => (s2 desc, idx asc), jax tie order.
// ============================================================================
__global__ void __launch_bounds__(1024, 1)
k_topk(const int* __restrict__ sector, const unsigned char* __restrict__ am) {
    pdl_trigger();                      // let k_emit launch immediately
    int sec  = blockIdx.x;
    int tid  = threadIdx.x;
    int lane = tid & 31, wp = tid >> 5;

    int mode = detect_mode<1024>(am);   // independent of k_scores

    __shared__ int idxs[CAP];
    __shared__ unsigned long long keys[CAP];
    __shared__ int s_n;
    if (tid == 0) s_n = 0;
    __syncthreads();

    // ---- compact member indices (independent of scores) ----
#pragma unroll 1
    for (int it = 0; it < NN / 1024; it++) {
        int i = tid + (it << 10);
        bool mem = (sector[i] == sec) && is_active(am, i, mode);
        unsigned bal = __ballot_sync(0xFFFFFFFFu, mem);
        int nb  = __popc(bal);
        int ldr = nb ? (__ffs(bal) - 1) : 0;
        int base = 0;
        if (nb && lane == ldr) base = atomicAdd(&s_n, nb);
        base = __shfl_sync(0xFFFFFFFFu, base, ldr);
        if (mem) {
            int pos = base + __popc(bal & ((1u << lane) - 1u));
            if (pos < CAP) idxs[pos] = i;
        }
    }
    __syncthreads();
    int M = s_n < CAP ? s_n : CAP;

    pdl_wait();                         // scores now final

    // ---- build keys for compacted members only ----
    for (int j = tid; j < M; j += 1024) {
        int i = idxs[j];
        float s2 = sum_row(g_p2T[i]);
        unsigned u = __float_as_uint(s2);
        u = (u & 0x80000000u) ? ~u : (u | 0x80000000u);
        keys[j] = ((unsigned long long)u << 32) | (unsigned)(~i);
    }
    __syncthreads();

    // ---- single-warp tournament over M compacted keys ----
    if (wp == 0) {
        int cnt = 0;
#pragma unroll 1
        for (int r = 0; r < TOPK; r++) {
            unsigned long long m = 0ull;
            int mi = -1;
            for (int j = lane; j < M; j += 32) {
                unsigned long long v = keys[j];
                if (v > m) { m = v; mi = j; }
            }
            unsigned long long w = m;
#pragma unroll
            for (int o = 16; o; o >>= 1)
                w = umax64(w, __shfl_xor_sync(0xFFFFFFFFu, w, o));
            if (w == 0ull) break;
            if (m == w && mi >= 0) keys[mi] = 0ull;    // unique key -> one lane
            if (lane == 0) {
                unsigned hi = (unsigned)(w >> 32);
                g_tidx[sec][r] = (int)(~(unsigned)(w & 0xFFFFFFFFull));
                g_ts2[sec][r]  = __uint_as_float(
                    (hi & 0x80000000u) ? (hi & 0x7FFFFFFFu) : ~hi);
            }
            cnt = r + 1;
        }
        if (lane == 0) {
            // fill remaining slots with smallest NON-member indices (-inf
            // ties; jax top_k picks them in ascending index order)
            int k = cnt, j = 0;
            while (k < TOPK && j < NN) {
                bool mem = (sector[j] == sec) && is_active(am, j, mode);
                if (!mem) { g_tidx[sec][k] = j; g_ts2[sec][k] = 0.f; k++; }
                j++;
            }
            while (k < TOPK) { g_tidx[sec][k] = 0; g_ts2[sec][k] = 0.f; k++; }
            g_tcnt[sec] = cnt;
        }
    }
}

// ============================================================================
// Kernel 3 (64 blocks, 512 threads), PDL-secondary to k_topk.
// Pre-sync: local detect + row preamble (act, sector). Post-sync: s1 sum,
// sector tables, emit. thread = (row, k-quad).
// ============================================================================
__global__ void __launch_bounds__(512, 1)
k_emit(const int* __restrict__ sector, const unsigned char* __restrict__ am,
       float* __restrict__ out, int out_size) {
    int t = threadIdx.x;
    int mode = detect_mode<512>(am);    // independent preamble

    int rl   = t >> 2;                  // local row 0..127
    int quad = t & 3;                   // which k-quad
    int row  = blockIdx.x * 128 + rl;
    bool act = is_active(am, row, mode);
    int  sc  = sector[row];

    pdl_wait();                         // k_topk tables + k_scores partials final

    float s1 = 0.f;
    if (act) s1 = sum_row(g_p1T[row]);

    __shared__ int   s_idx[NSEC][TOPK];
    __shared__ float s_s2[NSEC][TOPK];
    __shared__ int   s_cnt[NSEC];
    for (int q = t; q < NSEC * TOPK; q += 512) {
        int s = q >> 4, k = q & 15;
        s_idx[s][k] = g_tidx[s][k];
        s_s2[s][k]  = g_ts2[s][k];
        if (k == 0) s_cnt[s] = g_tcnt[s];
    }
    __syncthreads();

    int cnt = s_cnt[sc];
    const int NT = NN * TOPK;
    bool w_idx = (out_size >= 2 * NT);
    bool w_val = (out_size >= 3 * NT);
    float wv[4], iv[4], vv[4];
#pragma unroll
    for (int q = 0; q < 4; q++) {
        int kk = quad * 4 + q;
        if (!act) {
            // whole row is -inf: top_k returns indices 0..15, invalid
            wv[q] = 0.f; iv[q] = (float)kk; vv[q] = 0.f;
        } else if (kk < cnt) {
            float x = s1 + s_s2[sc][kk];
            wv[q] = (x >= 0.f) ? x : NEG_SLOPE * x;   // leaky_relu, T=1
            iv[q] = (float)s_idx[sc][kk]; vv[q] = 1.f;
        } else {
            wv[q] = 0.f; iv[q] = (float)s_idx[sc][kk]; vv[q] = 0.f;
        }
    }
    int o = row * TOPK + quad * 4;
    *(float4*)&out[o] = make_float4(wv[0], wv[1], wv[2], wv[3]);
    if (w_idx) *(float4*)&out[NT + o]     = make_float4(iv[0], iv[1], iv[2], iv[3]);
    if (w_val) *(float4*)&out[2 * NT + o] = make_float4(vv[0], vv[1], vv[2], vv[3]);
}

// ---------------- host ----------------
template <typename K, typename... Args>
static inline void launch_pdl(K kern, dim3 grid, dim3 block, Args... args) {
    cudaLaunchConfig_t cfg = {};
    cfg.gridDim = grid;
    cfg.blockDim = block;
    cudaLaunchAttribute at[1];
    at[0].id = cudaLaunchAttributeProgrammaticStreamSerialization;
    at[0].val.programmaticStreamSerializationAllowed = 1;
    cfg.attrs = at;
    cfg.numAttrs = 1;
    if (cudaLaunchKernelEx(&cfg, kern, args...) != cudaSuccess) {
        kern<<<grid, block>>>(args...);   // fallback: plain launch
    }
}

extern "C" void kernel_launch(void* const* d_in, const int* in_sizes, int n_in,
                              void* d_out, int out_size) {
    const float* E      = (const float*)d_in[0];   // embeddings [N, H]
    const float* W      = (const float*)d_in[1];   // W [H, H]
    const float* a      = (const float*)d_in[2];   // a [2H]
    const int*   sector = (const int*)d_in[3];     // sector_ids [N]
    const unsigned char* am = (const unsigned char*)d_in[4];  // active_mask
    float* out = (float*)d_out;

    k_scores<<<CCH * NTILE, 256>>>(E, W, a);
    launch_pdl(k_topk, dim3(NSEC), dim3(1024), sector, am);
    launch_pdl(k_emit, dim3(NN / 128), dim3(512), sector, am, out, out_size);
}